// round 14
// baseline (speedup 1.0000x reference)
#include <cuda_runtime.h>
#include <math.h>

#define B_DIM 128
#define T_DIM 4096
#define C_DIM 64
#define N_KNOT 6

// -------- scratch & constants (no allocation allowed) --------
__device__ float d_LU[N_KNOT][N_KNOT];   // netlib sgetf2 packed L(unit)+U
__device__ float d_Uinv[N_KNOT];         // fl(1/U[k][k])
__device__ int   d_perm[N_KNOT];
__device__ float d_scratch[(size_t)B_DIM * C_DIM * T_DIM]; // [B,C,T], in-place

// reciprocal constants (correctly-rounded host folds, same as XLA's rewrite)
#define R819   (1.0f / 819.0f)
#define R6C    (1.0f / 6.0f)
#define R4914  (1.0f / 4914.0f)

// -------- setup: netlib sgetf2 (recip-scale + fma sger), fp32 --------
__global__ void setup_kernel() {
    if (threadIdx.x != 0 || blockIdx.x != 0) return;
    float A[N_KNOT][N_KNOT];
    for (int i = 0; i < N_KNOT; i++)
        for (int j = 0; j < N_KNOT; j++) A[i][j] = 0.0f;
    const float h = 819.0f;
    A[0][0] = -1.0f; A[0][1] = 2.0f; A[0][2] = -1.0f;
    for (int i = 1; i <= 4; i++) { A[i][i-1] = h; A[i][i] = 4.0f*h; A[i][i+1] = h; }
    A[5][3] = -1.0f; A[5][4] = 2.0f; A[5][5] = -1.0f;

    int ipiv[N_KNOT];
    for (int j = 0; j < N_KNOT; j++) {
        int p = j;
        float best = fabsf(A[j][j]);
        for (int i = j + 1; i < N_KNOT; i++) {
            float v = fabsf(A[i][j]);
            if (v > best) { best = v; p = i; }
        }
        ipiv[j] = p;
        if (p != j) {
            for (int k = 0; k < N_KNOT; k++) {
                float t = A[j][k]; A[j][k] = A[p][k]; A[p][k] = t;
            }
        }
        float r = __fdiv_rn(1.0f, A[j][j]);
        for (int i = j + 1; i < N_KNOT; i++)
            A[i][j] = __fmul_rn(A[i][j], r);
        for (int k = j + 1; k < N_KNOT; k++) {
            float temp = -A[j][k];
            for (int i = j + 1; i < N_KNOT; i++)
                A[i][k] = __fmaf_rn(A[i][j], temp, A[i][k]);
        }
    }
    int perm[N_KNOT];
    for (int i = 0; i < N_KNOT; i++) perm[i] = i;
    for (int j = 0; j < N_KNOT; j++) {
        int p = ipiv[j];
        int t = perm[j]; perm[j] = perm[p]; perm[p] = t;
    }
    for (int i = 0; i < N_KNOT; i++) {
        d_perm[i] = perm[i];
        for (int j = 0; j < N_KNOT; j++) d_LU[i][j] = A[i][j];
        d_Uinv[i] = __fdiv_rn(1.0f, A[i][i]);
    }
}

// -------- transpose [B,T,C] -> [B,C,T], float4 both sides --------
// tile: 32 t-rows x 64 channels; grid (T/32, B)
__global__ __launch_bounds__(256)
void transpose_btc_to_bct(const float* __restrict__ in, float* __restrict__ out) {
    __shared__ float tile[32][65];
    const int b = blockIdx.y;
    const int t0 = blockIdx.x * 32;
    const int tid = threadIdx.x;
    const float* inb = in + (size_t)b * T_DIM * C_DIM;
    float* outb = out + (size_t)b * T_DIM * C_DIM;

    #pragma unroll
    for (int i = 0; i < 2; i++) {
        const int tid2 = tid + i * 256;
        const int t = tid2 >> 4;
        const int c4 = (tid2 & 15) << 2;
        float4 v = *reinterpret_cast<const float4*>(inb + (size_t)(t0 + t) * C_DIM + c4);
        tile[t][c4 + 0] = v.x; tile[t][c4 + 1] = v.y;
        tile[t][c4 + 2] = v.z; tile[t][c4 + 3] = v.w;
    }
    __syncthreads();

    const int c = tid >> 2;
    const int seg = tid & 3;
    #pragma unroll
    for (int u = 0; u < 2; u++) {
        const int t = seg * 4 + u * 16;
        float4 w = make_float4(tile[t][c], tile[t + 1][c], tile[t + 2][c], tile[t + 3][c]);
        *reinterpret_cast<float4*>(outb + (size_t)c * T_DIM + t0 + t) = w;
    }
}

// -------- transpose [B,C,T] -> [B,T,C], float4 both sides --------
// tile: 64 channels x 32 t; grid (T/32, B)
__global__ __launch_bounds__(256)
void transpose_bct_to_btc(const float* __restrict__ in, float* __restrict__ out) {
    __shared__ float tile[64][33];
    const int b = blockIdx.y;
    const int t0 = blockIdx.x * 32;
    const int tid = threadIdx.x;
    const float* inb = in + (size_t)b * T_DIM * C_DIM;
    float* outb = out + (size_t)b * T_DIM * C_DIM;

    #pragma unroll
    for (int i = 0; i < 2; i++) {
        const int tid2 = tid + i * 256;
        const int c = tid2 >> 3;
        const int t4 = (tid2 & 7) << 2;
        float4 v = *reinterpret_cast<const float4*>(inb + (size_t)c * T_DIM + t0 + t4);
        tile[c][t4 + 0] = v.x; tile[c][t4 + 1] = v.y;
        tile[c][t4 + 2] = v.z; tile[c][t4 + 3] = v.w;
    }
    __syncthreads();

    const int t = tid >> 3;
    const int cs = tid & 7;
    #pragma unroll
    for (int u = 0; u < 2; u++) {
        const int c = cs * 4 + u * 32;
        float4 w = make_float4(tile[c][t], tile[c + 1][t], tile[c + 2][t], tile[c + 3][t]);
        *reinterpret_cast<float4*>(outb + (size_t)(t0 + t) * C_DIM + c) = w;
    }
}

// -------- main per-series kernel (C1 numeric path; 512 threads, ILP-2 search) --------
__global__ __launch_bounds__(512)
void warp_interp_kernel(const float* __restrict__ warps,
                        float* __restrict__ series /* [B,C,T], in-place */) {
    __shared__ float s_xp[T_DIM];
    __shared__ float s_fp[T_DIM];

    const int c = blockIdx.x;
    const int b = blockIdx.y;
    const int tid = threadIdx.x;
    float* row = series + ((size_t)b * C_DIM + c) * T_DIM;

    // ---- redundant per-thread solve (identical fp ops -> identical bits) ----
    float y[N_KNOT], M[N_KNOT];
    {
        float r[N_KNOT];
        #pragma unroll
        for (int k = 0; k < N_KNOT; k++)
            r[k] = warps[((size_t)b * N_KNOT + k) * C_DIM + c];   // random_warps[b,k,c]
        #pragma unroll
        for (int k = 0; k < N_KNOT; k++)
            y[k] = __fmul_rn(819.0f * (float)k, r[k]);            // y = w*r

        float rhs[N_KNOT];
        rhs[0] = 0.0f; rhs[5] = 0.0f;
        #pragma unroll
        for (int i = 1; i <= 4; i++) {
            float t1 = __fmul_rn(2.0f, y[i]);
            float t2 = __fsub_rn(y[i + 1], t1);
            float t3 = __fadd_rn(t2, y[i - 1]);
            float t4 = __fmul_rn(6.0f, t3);
            rhs[i] = __fmul_rn(t4, R819);
        }

        float bb[N_KNOT];
        #pragma unroll
        for (int i = 0; i < N_KNOT; i++) bb[i] = rhs[d_perm[i]];
        #pragma unroll
        for (int k = 0; k < N_KNOT; k++) {
            if (bb[k] != 0.0f) {
                #pragma unroll
                for (int i = k + 1; i < N_KNOT; i++)
                    bb[i] = __fmaf_rn(-bb[k], d_LU[i][k], bb[i]);
            }
        }
        #pragma unroll
        for (int k = N_KNOT - 1; k >= 0; k--) {
            if (bb[k] != 0.0f) {
                bb[k] = __fmul_rn(bb[k], d_Uinv[k]);
                #pragma unroll
                for (int i = 0; i < k; i++)
                    bb[i] = __fmaf_rn(-bb[k], d_LU[i][k], bb[i]);
            }
        }
        #pragma unroll
        for (int k = 0; k < N_KNOT; k++) M[k] = bb[k];
    }

    // tw evaluator, frozen op order (XLA recip-mult constant rewrite)
    auto eval_tw = [&](int idx, float t) -> float {
        const float y0 = y[idx], y1 = y[idx + 1];
        const float M0 = M[idx], M1 = M[idx + 1];
        float a  = __fsub_rn(y1, y0);
        float bq = __fmul_rn(a, R819);
        float cq = __fmul_rn(2.0f, M0);
        float dq = __fadd_rn(cq, M1);
        float eq = __fmul_rn(819.0f, dq);
        float fq2 = __fmul_rn(eq, R6C);
        float c1 = __fsub_rn(bq, fq2);
        float g1 = __fmul_rn(t, c1);
        float s1 = __fadd_rn(y0, g1);
        float tt = __fmul_rn(t, t);
        float m02 = __fmul_rn(M0, 0.5f);
        float q1 = __fmul_rn(tt, m02);
        float s2 = __fadd_rn(s1, q1);
        float ttt = __fmul_rn(tt, t);
        float dm = __fsub_rn(M1, M0);
        float kk = __fmul_rn(dm, R4914);
        float q2 = __fmul_rn(ttt, kk);
        return __fadd_rn(s2, q2);
    };

    const float scale = __fdiv_rn(4095.0f, eval_tw(4, 819.0f));

    // ---- fills (strided, coalesced; no prior sync needed) ----
    #pragma unroll
    for (int j = tid; j < T_DIM; j += 512) {
        const float xq = (float)j;
        int idx = (int)__fmul_rn(xq, R819);
        idx = idx < 0 ? 0 : (idx > 4 ? 4 : idx);
        const float t = __fsub_rn(xq, 819.0f * (float)idx);
        float tw = eval_tw(idx, t);
        float xpv = __fmul_rn(scale, tw);
        xpv = fminf(fmaxf(xpv, 0.0f), 4095.0f);
        s_xp[j] = xpv;
        s_fp[j] = row[j];
    }
    __syncthreads();

    const float xp0 = s_xp[0],       xpN = s_xp[T_DIM - 1];
    const float fp0 = s_fp[0],       fpN = s_fp[T_DIM - 1];

    // exact interp, frozen ops
    auto interp_one = [&](int q) -> float {
        const float fq = (float)q;
        int lo = 0, hi = T_DIM;
        #pragma unroll
        for (int s = 0; s < 13; s++) {
            const int mid = (lo + hi) >> 1;
            const bool go_left = fq < s_xp[mid];
            lo = go_left ? lo : mid;
            hi = go_left ? mid : hi;
        }
        int i = hi;
        i = i < 1 ? 1 : (i > T_DIM - 1 ? T_DIM - 1 : i);

        const float x0 = s_xp[i - 1], x1 = s_xp[i];
        const float f0 = s_fp[i - 1], f1 = s_fp[i];
        const float dx = __fsub_rn(x1, x0);
        float f;
        if (fabsf(dx) <= 1.4210855e-14f) {
            f = f0;                                      // JAX: fp[i-1] when dx ~ 0
        } else {
            const float df    = __fsub_rn(f1, f0);
            const float delta = __fsub_rn(fq, x0);
            const float ratio = __fdiv_rn(delta, dx);
            const float prod  = __fmul_rn(ratio, df);
            f = __fadd_rn(f0, prod);
        }
        if (fq < xp0) f = fp0;
        if (fq > xpN) f = fpN;
        return f;
    };

    // 2-query ILP: two independent 13-level chains in flight per iteration
    #pragma unroll
    for (int q = tid; q < T_DIM; q += 1024) {
        const float fa = interp_one(q);
        const float fb = interp_one(q + 512);
        row[q]       = fa;
        row[q + 512] = fb;
    }
}

extern "C" void kernel_launch(void* const* d_in, const int* in_sizes, int n_in,
                              void* d_out, int out_size) {
    const float* x = (const float*)d_in[0];
    const float* w = (const float*)d_in[1];
    if (n_in >= 2 && in_sizes[0] < in_sizes[1]) {        // x is the big tensor
        x = (const float*)d_in[1];
        w = (const float*)d_in[0];
    }
    float* out = (float*)d_out;

    float* scratch = nullptr;
    cudaGetSymbolAddress((void**)&scratch, d_scratch);

    setup_kernel<<<1, 1>>>();

    dim3 gT(T_DIM / 32, B_DIM);
    transpose_btc_to_bct<<<gT, 256>>>(x, scratch);

    dim3 gW(C_DIM, B_DIM);
    warp_interp_kernel<<<gW, 512>>>(w, scratch);

    transpose_bct_to_btc<<<gT, 256>>>(scratch, out);
}

// round 15
// speedup vs baseline: 1.1678x; 1.1678x over previous
#include <cuda_runtime.h>
#include <math.h>

#define B_DIM 128
#define T_DIM 4096
#define C_DIM 64
#define N_KNOT 6

// -------- scratch & constants (no allocation allowed) --------
__device__ float d_LU[N_KNOT][N_KNOT];   // netlib sgetf2 packed L(unit)+U
__device__ float d_Uinv[N_KNOT];         // fl(1/U[k][k])
__device__ int   d_perm[N_KNOT];
__device__ float d_scratch[(size_t)B_DIM * C_DIM * T_DIM]; // [B,C,T], in-place

// reciprocal constants (correctly-rounded host folds, same as XLA's rewrite)
#define R819   (1.0f / 819.0f)
#define R6C    (1.0f / 6.0f)
#define R4914  (1.0f / 4914.0f)

// -------- setup: netlib sgetf2 (recip-scale + fma sger), fp32 --------
__global__ void setup_kernel() {
    if (threadIdx.x != 0 || blockIdx.x != 0) return;
    float A[N_KNOT][N_KNOT];
    for (int i = 0; i < N_KNOT; i++)
        for (int j = 0; j < N_KNOT; j++) A[i][j] = 0.0f;
    const float h = 819.0f;
    A[0][0] = -1.0f; A[0][1] = 2.0f; A[0][2] = -1.0f;
    for (int i = 1; i <= 4; i++) { A[i][i-1] = h; A[i][i] = 4.0f*h; A[i][i+1] = h; }
    A[5][3] = -1.0f; A[5][4] = 2.0f; A[5][5] = -1.0f;

    int ipiv[N_KNOT];
    for (int j = 0; j < N_KNOT; j++) {
        int p = j;
        float best = fabsf(A[j][j]);
        for (int i = j + 1; i < N_KNOT; i++) {
            float v = fabsf(A[i][j]);
            if (v > best) { best = v; p = i; }
        }
        ipiv[j] = p;
        if (p != j) {
            for (int k = 0; k < N_KNOT; k++) {
                float t = A[j][k]; A[j][k] = A[p][k]; A[p][k] = t;
            }
        }
        float r = __fdiv_rn(1.0f, A[j][j]);
        for (int i = j + 1; i < N_KNOT; i++)
            A[i][j] = __fmul_rn(A[i][j], r);
        for (int k = j + 1; k < N_KNOT; k++) {
            float temp = -A[j][k];
            for (int i = j + 1; i < N_KNOT; i++)
                A[i][k] = __fmaf_rn(A[i][j], temp, A[i][k]);
        }
    }
    int perm[N_KNOT];
    for (int i = 0; i < N_KNOT; i++) perm[i] = i;
    for (int j = 0; j < N_KNOT; j++) {
        int p = ipiv[j];
        int t = perm[j]; perm[j] = perm[p]; perm[p] = t;
    }
    for (int i = 0; i < N_KNOT; i++) {
        d_perm[i] = perm[i];
        for (int j = 0; j < N_KNOT; j++) d_LU[i][j] = A[i][j];
        d_Uinv[i] = __fdiv_rn(1.0f, A[i][i]);
    }
}

// -------- transpose [B,T,C] -> [B,C,T], float4 both sides --------
// tile: 32 t-rows x 64 channels; grid (T/32, B)
__global__ __launch_bounds__(256)
void transpose_btc_to_bct(const float* __restrict__ in, float* __restrict__ out) {
    __shared__ float tile[32][65];
    const int b = blockIdx.y;
    const int t0 = blockIdx.x * 32;
    const int tid = threadIdx.x;
    const float* inb = in + (size_t)b * T_DIM * C_DIM;
    float* outb = out + (size_t)b * T_DIM * C_DIM;

    #pragma unroll
    for (int i = 0; i < 2; i++) {
        const int tid2 = tid + i * 256;
        const int t = tid2 >> 4;
        const int c4 = (tid2 & 15) << 2;
        float4 v = *reinterpret_cast<const float4*>(inb + (size_t)(t0 + t) * C_DIM + c4);
        tile[t][c4 + 0] = v.x; tile[t][c4 + 1] = v.y;
        tile[t][c4 + 2] = v.z; tile[t][c4 + 3] = v.w;
    }
    __syncthreads();

    const int c = tid >> 2;
    const int seg = tid & 3;
    #pragma unroll
    for (int u = 0; u < 2; u++) {
        const int t = seg * 4 + u * 16;
        float4 w = make_float4(tile[t][c], tile[t + 1][c], tile[t + 2][c], tile[t + 3][c]);
        *reinterpret_cast<float4*>(outb + (size_t)c * T_DIM + t0 + t) = w;
    }
}

// -------- transpose [B,C,T] -> [B,T,C], float4 both sides --------
// tile: 64 channels x 32 t; grid (T/32, B)
__global__ __launch_bounds__(256)
void transpose_bct_to_btc(const float* __restrict__ in, float* __restrict__ out) {
    __shared__ float tile[64][33];
    const int b = blockIdx.y;
    const int t0 = blockIdx.x * 32;
    const int tid = threadIdx.x;
    const float* inb = in + (size_t)b * T_DIM * C_DIM;
    float* outb = out + (size_t)b * T_DIM * C_DIM;

    #pragma unroll
    for (int i = 0; i < 2; i++) {
        const int tid2 = tid + i * 256;
        const int c = tid2 >> 3;
        const int t4 = (tid2 & 7) << 2;
        float4 v = *reinterpret_cast<const float4*>(inb + (size_t)c * T_DIM + t0 + t4);
        tile[c][t4 + 0] = v.x; tile[c][t4 + 1] = v.y;
        tile[c][t4 + 2] = v.z; tile[c][t4 + 3] = v.w;
    }
    __syncthreads();

    const int t = tid >> 3;
    const int cs = tid & 7;
    #pragma unroll
    for (int u = 0; u < 2; u++) {
        const int c = cs * 4 + u * 32;
        float4 w = make_float4(tile[c][t], tile[c + 1][t], tile[c + 2][t], tile[c + 3][t]);
        *reinterpret_cast<float4*>(outb + (size_t)(t0 + t) * C_DIM + c) = w;
    }
}

// -------- main per-series kernel: R10 verbatim (fastest measured variant) --------
__global__ __launch_bounds__(256)
void warp_interp_kernel(const float* __restrict__ warps,
                        float* __restrict__ series /* [B,C,T], in-place */) {
    __shared__ float s_xp[T_DIM];
    __shared__ float s_fp[T_DIM];
    __shared__ float s_y[N_KNOT];
    __shared__ float s_M[N_KNOT];

    const int c = blockIdx.x;
    const int b = blockIdx.y;
    const int tid = threadIdx.x;
    float* row = series + ((size_t)b * C_DIM + c) * T_DIM;

    if (tid == 0) {
        float r[N_KNOT], y[N_KNOT];
        #pragma unroll
        for (int k = 0; k < N_KNOT; k++)
            r[k] = warps[((size_t)b * N_KNOT + k) * C_DIM + c];   // random_warps[b,k,c]
        #pragma unroll
        for (int k = 0; k < N_KNOT; k++)
            y[k] = __fmul_rn(819.0f * (float)k, r[k]);            // y = w*r

        // rhs[i] = (6*((y[i+1]-2*y[i]) + y[i-1])) * fl(1/819)
        float rhs[N_KNOT];
        rhs[0] = 0.0f; rhs[5] = 0.0f;
        #pragma unroll
        for (int i = 1; i <= 4; i++) {
            float t1 = __fmul_rn(2.0f, y[i]);
            float t2 = __fsub_rn(y[i + 1], t1);
            float t3 = __fadd_rn(t2, y[i - 1]);
            float t4 = __fmul_rn(6.0f, t3);
            rhs[i] = __fmul_rn(t4, R819);
        }

        // P*b gather, then axpy fwd (unit L) + axpy bwd with recip-mult diag
        float bb[N_KNOT];
        #pragma unroll
        for (int i = 0; i < N_KNOT; i++) bb[i] = rhs[d_perm[i]];
        #pragma unroll
        for (int k = 0; k < N_KNOT; k++) {
            if (bb[k] != 0.0f) {
                #pragma unroll
                for (int i = k + 1; i < N_KNOT; i++)
                    bb[i] = __fmaf_rn(-bb[k], d_LU[i][k], bb[i]);
            }
        }
        #pragma unroll
        for (int k = N_KNOT - 1; k >= 0; k--) {
            if (bb[k] != 0.0f) {
                bb[k] = __fmul_rn(bb[k], d_Uinv[k]);
                #pragma unroll
                for (int i = 0; i < k; i++)
                    bb[i] = __fmaf_rn(-bb[k], d_LU[i][k], bb[i]);
            }
        }
        #pragma unroll
        for (int k = 0; k < N_KNOT; k++) { s_y[k] = y[k]; s_M[k] = bb[k]; }
    }
    __syncthreads();

    // tw evaluator, frozen op order (XLA recip-mult constant rewrite)
    auto eval_tw = [&](int idx, float t) -> float {
        const float y0 = s_y[idx], y1 = s_y[idx + 1];
        const float M0 = s_M[idx], M1 = s_M[idx + 1];
        float a  = __fsub_rn(y1, y0);
        float bq = __fmul_rn(a, R819);
        float cq = __fmul_rn(2.0f, M0);
        float dq = __fadd_rn(cq, M1);
        float eq = __fmul_rn(819.0f, dq);
        float fq2 = __fmul_rn(eq, R6C);
        float c1 = __fsub_rn(bq, fq2);
        float g1 = __fmul_rn(t, c1);
        float s1 = __fadd_rn(y0, g1);
        float tt = __fmul_rn(t, t);
        float m02 = __fmul_rn(M0, 0.5f);
        float q1 = __fmul_rn(tt, m02);
        float s2 = __fadd_rn(s1, q1);
        float ttt = __fmul_rn(tt, t);
        float dm = __fsub_rn(M1, M0);
        float kk = __fmul_rn(dm, R4914);
        float q2 = __fmul_rn(ttt, kk);
        return __fadd_rn(s2, q2);
    };

    const float scale = __fdiv_rn(4095.0f, eval_tw(4, 819.0f));

    for (int j = tid; j < T_DIM; j += 256) {
        const float xq = (float)j;
        int idx = (int)__fmul_rn(xq, R819);              // xq/h -> xq*fl(1/819), trunc
        idx = idx < 0 ? 0 : (idx > 4 ? 4 : idx);
        const float t = __fsub_rn(xq, 819.0f * (float)idx);
        float tw = eval_tw(idx, t);
        float xpv = __fmul_rn(scale, tw);
        xpv = fminf(fmaxf(xpv, 0.0f), 4095.0f);
        s_xp[j] = xpv;
        s_fp[j] = row[j];
    }
    __syncthreads();

    const float xp0 = s_xp[0],       xpN = s_xp[T_DIM - 1];
    const float fp0 = s_fp[0],       fpN = s_fp[T_DIM - 1];

    for (int q = tid; q < T_DIM; q += 256) {
        const float fq = (float)q;
        // jnp.searchsorted 'scan', side='right': (0, n) init, 13 levels, return high
        int lo = 0, hi = T_DIM;
        #pragma unroll
        for (int s = 0; s < 13; s++) {
            const int mid = (lo + hi) >> 1;
            const bool go_left = fq < s_xp[mid];
            lo = go_left ? lo : mid;
            hi = go_left ? mid : hi;
        }
        int i = hi;
        i = i < 1 ? 1 : (i > T_DIM - 1 ? T_DIM - 1 : i);

        const float x0 = s_xp[i - 1], x1 = s_xp[i];
        const float f0 = s_fp[i - 1], f1 = s_fp[i];
        const float dx = __fsub_rn(x1, x0);
        float f;
        if (fabsf(dx) <= 1.4210855e-14f) {
            f = f0;                                      // JAX: fp[i-1] when dx ~ 0
        } else {
            const float df    = __fsub_rn(f1, f0);
            const float delta = __fsub_rn(fq, x0);
            const float ratio = __fdiv_rn(delta, dx);
            const float prod  = __fmul_rn(ratio, df);
            f = __fadd_rn(f0, prod);
        }
        if (fq < xp0) f = fp0;
        if (fq > xpN) f = fpN;
        row[q] = f;                                      // in-place, coalesced
    }
}

extern "C" void kernel_launch(void* const* d_in, const int* in_sizes, int n_in,
                              void* d_out, int out_size) {
    const float* x = (const float*)d_in[0];
    const float* w = (const float*)d_in[1];
    if (n_in >= 2 && in_sizes[0] < in_sizes[1]) {        // x is the big tensor
        x = (const float*)d_in[1];
        w = (const float*)d_in[0];
    }
    float* out = (float*)d_out;

    float* scratch = nullptr;
    cudaGetSymbolAddress((void**)&scratch, d_scratch);

    setup_kernel<<<1, 1>>>();

    dim3 gT(T_DIM / 32, B_DIM);
    transpose_btc_to_bct<<<gT, 256>>>(x, scratch);

    dim3 gW(C_DIM, B_DIM);
    warp_interp_kernel<<<gW, 256>>>(w, scratch);

    transpose_bct_to_btc<<<gT, 256>>>(scratch, out);
}

// round 16
// speedup vs baseline: 1.2105x; 1.0366x over previous
#include <cuda_runtime.h>
#include <math.h>

#define B_DIM 128
#define T_DIM 4096
#define C_DIM 64
#define N_KNOT 6

// -------- scratch & constants (no allocation allowed) --------
__device__ float d_LU[N_KNOT][N_KNOT];   // netlib sgetf2 packed L(unit)+U
__device__ float d_Uinv[N_KNOT];         // fl(1/U[k][k])
__device__ int   d_perm[N_KNOT];
__device__ float d_scratch[(size_t)B_DIM * C_DIM * T_DIM]; // [B,C,T], in-place

// reciprocal constants (correctly-rounded host folds, same as XLA's rewrite)
#define R819   (1.0f / 819.0f)
#define R6C    (1.0f / 6.0f)
#define R4914  (1.0f / 4914.0f)

// -------- setup: netlib sgetf2 (recip-scale + fma sger), fp32 --------
__global__ void setup_kernel() {
    if (threadIdx.x != 0 || blockIdx.x != 0) return;
    float A[N_KNOT][N_KNOT];
    for (int i = 0; i < N_KNOT; i++)
        for (int j = 0; j < N_KNOT; j++) A[i][j] = 0.0f;
    const float h = 819.0f;
    A[0][0] = -1.0f; A[0][1] = 2.0f; A[0][2] = -1.0f;
    for (int i = 1; i <= 4; i++) { A[i][i-1] = h; A[i][i] = 4.0f*h; A[i][i+1] = h; }
    A[5][3] = -1.0f; A[5][4] = 2.0f; A[5][5] = -1.0f;

    int ipiv[N_KNOT];
    for (int j = 0; j < N_KNOT; j++) {
        int p = j;
        float best = fabsf(A[j][j]);
        for (int i = j + 1; i < N_KNOT; i++) {
            float v = fabsf(A[i][j]);
            if (v > best) { best = v; p = i; }
        }
        ipiv[j] = p;
        if (p != j) {
            for (int k = 0; k < N_KNOT; k++) {
                float t = A[j][k]; A[j][k] = A[p][k]; A[p][k] = t;
            }
        }
        float r = __fdiv_rn(1.0f, A[j][j]);
        for (int i = j + 1; i < N_KNOT; i++)
            A[i][j] = __fmul_rn(A[i][j], r);
        for (int k = j + 1; k < N_KNOT; k++) {
            float temp = -A[j][k];
            for (int i = j + 1; i < N_KNOT; i++)
                A[i][k] = __fmaf_rn(A[i][j], temp, A[i][k]);
        }
    }
    int perm[N_KNOT];
    for (int i = 0; i < N_KNOT; i++) perm[i] = i;
    for (int j = 0; j < N_KNOT; j++) {
        int p = ipiv[j];
        int t = perm[j]; perm[j] = perm[p]; perm[p] = t;
    }
    for (int i = 0; i < N_KNOT; i++) {
        d_perm[i] = perm[i];
        for (int j = 0; j < N_KNOT; j++) d_LU[i][j] = A[i][j];
        d_Uinv[i] = __fdiv_rn(1.0f, A[i][i]);
    }
}

// -------- transpose [B,T,C] -> [B,C,T], float4 both sides --------
// tile: 32 t-rows x 64 channels; grid (T/32, B)
__global__ __launch_bounds__(256)
void transpose_btc_to_bct(const float* __restrict__ in, float* __restrict__ out) {
    __shared__ float tile[32][65];
    const int b = blockIdx.y;
    const int t0 = blockIdx.x * 32;
    const int tid = threadIdx.x;
    const float* inb = in + (size_t)b * T_DIM * C_DIM;
    float* outb = out + (size_t)b * T_DIM * C_DIM;

    #pragma unroll
    for (int i = 0; i < 2; i++) {
        const int tid2 = tid + i * 256;
        const int t = tid2 >> 4;
        const int c4 = (tid2 & 15) << 2;
        float4 v = *reinterpret_cast<const float4*>(inb + (size_t)(t0 + t) * C_DIM + c4);
        tile[t][c4 + 0] = v.x; tile[t][c4 + 1] = v.y;
        tile[t][c4 + 2] = v.z; tile[t][c4 + 3] = v.w;
    }
    __syncthreads();

    const int c = tid >> 2;
    const int seg = tid & 3;
    #pragma unroll
    for (int u = 0; u < 2; u++) {
        const int t = seg * 4 + u * 16;
        float4 w = make_float4(tile[t][c], tile[t + 1][c], tile[t + 2][c], tile[t + 3][c]);
        *reinterpret_cast<float4*>(outb + (size_t)c * T_DIM + t0 + t) = w;
    }
}

// -------- transpose [B,C,T] -> [B,T,C], float4 both sides --------
// tile: 64 channels x 32 t; grid (T/32, B)
__global__ __launch_bounds__(256)
void transpose_bct_to_btc(const float* __restrict__ in, float* __restrict__ out) {
    __shared__ float tile[64][33];
    const int b = blockIdx.y;
    const int t0 = blockIdx.x * 32;
    const int tid = threadIdx.x;
    const float* inb = in + (size_t)b * T_DIM * C_DIM;
    float* outb = out + (size_t)b * T_DIM * C_DIM;

    #pragma unroll
    for (int i = 0; i < 2; i++) {
        const int tid2 = tid + i * 256;
        const int c = tid2 >> 3;
        const int t4 = (tid2 & 7) << 2;
        float4 v = *reinterpret_cast<const float4*>(inb + (size_t)c * T_DIM + t0 + t4);
        tile[c][t4 + 0] = v.x; tile[c][t4 + 1] = v.y;
        tile[c][t4 + 2] = v.z; tile[c][t4 + 3] = v.w;
    }
    __syncthreads();

    const int t = tid >> 3;
    const int cs = tid & 7;
    #pragma unroll
    for (int u = 0; u < 2; u++) {
        const int c = cs * 4 + u * 32;
        float4 w = make_float4(tile[c][t], tile[c + 1][t], tile[c + 2][t], tile[c + 3][t]);
        *reinterpret_cast<float4*>(outb + (size_t)(t0 + t) * C_DIM + c) = w;
    }
}

// -------- main per-series kernel: R10 structure + ILP-2 bisection --------
__global__ __launch_bounds__(256)
void warp_interp_kernel(const float* __restrict__ warps,
                        float* __restrict__ series /* [B,C,T], in-place */) {
    __shared__ float s_xp[T_DIM];
    __shared__ float s_fp[T_DIM];
    __shared__ float s_y[N_KNOT];
    __shared__ float s_M[N_KNOT];

    const int c = blockIdx.x;
    const int b = blockIdx.y;
    const int tid = threadIdx.x;
    float* row = series + ((size_t)b * C_DIM + c) * T_DIM;

    if (tid == 0) {
        float r[N_KNOT], y[N_KNOT];
        #pragma unroll
        for (int k = 0; k < N_KNOT; k++)
            r[k] = warps[((size_t)b * N_KNOT + k) * C_DIM + c];   // random_warps[b,k,c]
        #pragma unroll
        for (int k = 0; k < N_KNOT; k++)
            y[k] = __fmul_rn(819.0f * (float)k, r[k]);            // y = w*r

        // rhs[i] = (6*((y[i+1]-2*y[i]) + y[i-1])) * fl(1/819)
        float rhs[N_KNOT];
        rhs[0] = 0.0f; rhs[5] = 0.0f;
        #pragma unroll
        for (int i = 1; i <= 4; i++) {
            float t1 = __fmul_rn(2.0f, y[i]);
            float t2 = __fsub_rn(y[i + 1], t1);
            float t3 = __fadd_rn(t2, y[i - 1]);
            float t4 = __fmul_rn(6.0f, t3);
            rhs[i] = __fmul_rn(t4, R819);
        }

        // P*b gather, then axpy fwd (unit L) + axpy bwd with recip-mult diag
        float bb[N_KNOT];
        #pragma unroll
        for (int i = 0; i < N_KNOT; i++) bb[i] = rhs[d_perm[i]];
        #pragma unroll
        for (int k = 0; k < N_KNOT; k++) {
            if (bb[k] != 0.0f) {
                #pragma unroll
                for (int i = k + 1; i < N_KNOT; i++)
                    bb[i] = __fmaf_rn(-bb[k], d_LU[i][k], bb[i]);
            }
        }
        #pragma unroll
        for (int k = N_KNOT - 1; k >= 0; k--) {
            if (bb[k] != 0.0f) {
                bb[k] = __fmul_rn(bb[k], d_Uinv[k]);
                #pragma unroll
                for (int i = 0; i < k; i++)
                    bb[i] = __fmaf_rn(-bb[k], d_LU[i][k], bb[i]);
            }
        }
        #pragma unroll
        for (int k = 0; k < N_KNOT; k++) { s_y[k] = y[k]; s_M[k] = bb[k]; }
    }
    __syncthreads();

    // tw evaluator, frozen op order (XLA recip-mult constant rewrite)
    auto eval_tw = [&](int idx, float t) -> float {
        const float y0 = s_y[idx], y1 = s_y[idx + 1];
        const float M0 = s_M[idx], M1 = s_M[idx + 1];
        float a  = __fsub_rn(y1, y0);
        float bq = __fmul_rn(a, R819);
        float cq = __fmul_rn(2.0f, M0);
        float dq = __fadd_rn(cq, M1);
        float eq = __fmul_rn(819.0f, dq);
        float fq2 = __fmul_rn(eq, R6C);
        float c1 = __fsub_rn(bq, fq2);
        float g1 = __fmul_rn(t, c1);
        float s1 = __fadd_rn(y0, g1);
        float tt = __fmul_rn(t, t);
        float m02 = __fmul_rn(M0, 0.5f);
        float q1 = __fmul_rn(tt, m02);
        float s2 = __fadd_rn(s1, q1);
        float ttt = __fmul_rn(tt, t);
        float dm = __fsub_rn(M1, M0);
        float kk = __fmul_rn(dm, R4914);
        float q2 = __fmul_rn(ttt, kk);
        return __fadd_rn(s2, q2);
    };

    const float scale = __fdiv_rn(4095.0f, eval_tw(4, 819.0f));

    for (int j = tid; j < T_DIM; j += 256) {
        const float xq = (float)j;
        int idx = (int)__fmul_rn(xq, R819);              // xq/h -> xq*fl(1/819), trunc
        idx = idx < 0 ? 0 : (idx > 4 ? 4 : idx);
        const float t = __fsub_rn(xq, 819.0f * (float)idx);
        float tw = eval_tw(idx, t);
        float xpv = __fmul_rn(scale, tw);
        xpv = fminf(fmaxf(xpv, 0.0f), 4095.0f);
        s_xp[j] = xpv;
        s_fp[j] = row[j];
    }
    __syncthreads();

    const float xp0 = s_xp[0],       xpN = s_xp[T_DIM - 1];
    const float fp0 = s_fp[0],       fpN = s_fp[T_DIM - 1];

    // exact jnp scan replica for one query (frozen ops)
    auto interp_one = [&](int q) -> float {
        const float fq = (float)q;
        int lo = 0, hi = T_DIM;
        #pragma unroll
        for (int s = 0; s < 13; s++) {
            const int mid = (lo + hi) >> 1;
            const bool go_left = fq < s_xp[mid];
            lo = go_left ? lo : mid;
            hi = go_left ? mid : hi;
        }
        int i = hi;
        i = i < 1 ? 1 : (i > T_DIM - 1 ? T_DIM - 1 : i);

        const float x0 = s_xp[i - 1], x1 = s_xp[i];
        const float f0 = s_fp[i - 1], f1 = s_fp[i];
        const float dx = __fsub_rn(x1, x0);
        float f;
        if (fabsf(dx) <= 1.4210855e-14f) {
            f = f0;                                      // JAX: fp[i-1] when dx ~ 0
        } else {
            const float df    = __fsub_rn(f1, f0);
            const float delta = __fsub_rn(fq, x0);
            const float ratio = __fdiv_rn(delta, dx);
            const float prod  = __fmul_rn(ratio, df);
            f = __fadd_rn(f0, prod);
        }
        if (fq < xp0) f = fp0;
        if (fq > xpN) f = fpN;
        return f;
    };

    // ILP-2: two independent 13-level chains in flight per iteration
    for (int q = tid; q < T_DIM / 2; q += 256) {
        const float fa = interp_one(q);
        const float fb = interp_one(q + T_DIM / 2);
        row[q]              = fa;
        row[q + T_DIM / 2]  = fb;
    }
}

extern "C" void kernel_launch(void* const* d_in, const int* in_sizes, int n_in,
                              void* d_out, int out_size) {
    const float* x = (const float*)d_in[0];
    const float* w = (const float*)d_in[1];
    if (n_in >= 2 && in_sizes[0] < in_sizes[1]) {        // x is the big tensor
        x = (const float*)d_in[1];
        w = (const float*)d_in[0];
    }
    float* out = (float*)d_out;

    float* scratch = nullptr;
    cudaGetSymbolAddress((void**)&scratch, d_scratch);

    setup_kernel<<<1, 1>>>();

    dim3 gT(T_DIM / 32, B_DIM);
    transpose_btc_to_bct<<<gT, 256>>>(x, scratch);

    dim3 gW(C_DIM, B_DIM);
    warp_interp_kernel<<<gW, 256>>>(w, scratch);

    transpose_bct_to_btc<<<gT, 256>>>(scratch, out);
}